// round 2
// baseline (speedup 1.0000x reference)
#include <cuda_runtime.h>
#include <math.h>

// Problem constants (fixed by the reference)
#define NN 100000
#define NE 1600000
static constexpr int KDIM = 128;   // IN_DIM == HID_DIM == 128
static constexpr int HID  = 128;
static constexpr int OUTD = 64;

// ---------------- device scratch (allocation-free rule: __device__ globals) ---
__device__ float g_deg [NN];
__device__ float g_dinv[NN];
__device__ float g_h1  [(size_t)NN * HID];   // x @ W1
__device__ float g_agg1[(size_t)NN * HID];   // aggregated layer-1 (pre bias/relu)
__device__ float g_h2  [(size_t)NN * OUTD];  // relu(agg1+b1) @ W2

// ---------------- degree / normalization ------------------------------------
__global__ void k_init_deg() {
    int i = blockIdx.x * blockDim.x + threadIdx.x;
    if (i < NN) g_deg[i] = 1.0f;  // self-loop contributes 1
}

__global__ void k_deg(const int* __restrict__ tgt) {
    int e = blockIdx.x * blockDim.x + threadIdx.x;
    if (e < NE) atomicAdd(&g_deg[tgt[e]], 1.0f);
}

__global__ void k_dinv() {
    int i = blockIdx.x * blockDim.x + threadIdx.x;
    if (i < NN) g_dinv[i] = rsqrtf(g_deg[i]);
}

// ---------------- GEMM: C[BM x NC] tile, K=128 fully resident in smem --------
// 256 threads; each thread computes an 8x8 register tile.
// FUSE: apply x <- max(x + bias[k], 0) to the A-tile on load (layer-2 input).
template<int NC, bool FUSE>
__global__ void __launch_bounds__(256, 1)
k_gemm(const float* __restrict__ A, const float* __restrict__ W,
       const float* __restrict__ bin, float* __restrict__ C) {
    constexpr int TX = NC / 8;        // thread cols
    constexpr int TY = 256 / TX;      // thread rows
    constexpr int BM = TY * 8;        // rows per block
    constexpr int XSS = KDIM + 1;     // padded stride (129) to dodge bank conflicts

    extern __shared__ float sm[];
    float* xs = sm;                   // BM * XSS
    float* ws = sm + BM * XSS;        // KDIM * NC

    const int tid  = threadIdx.x;
    const int row0 = blockIdx.x * BM;

    // load W (KDIM x NC), row-major, vectorized
    for (int i = tid * 4; i < KDIM * NC; i += 256 * 4) {
        float4 v = *(const float4*)(W + i);
        ws[i + 0] = v.x; ws[i + 1] = v.y; ws[i + 2] = v.z; ws[i + 3] = v.w;
    }
    // load A tile (BM x KDIM), zero-padded past NN
    for (int i = tid * 4; i < BM * KDIM; i += 256 * 4) {
        int r = i / KDIM, c = i % KDIM;
        int gr = row0 + r;
        float4 v = make_float4(0.f, 0.f, 0.f, 0.f);
        if (gr < NN) v = *(const float4*)(A + (size_t)gr * KDIM + c);
        if (FUSE) {
            float4 b = *(const float4*)(bin + c);
            v.x = fmaxf(v.x + b.x, 0.f);
            v.y = fmaxf(v.y + b.y, 0.f);
            v.z = fmaxf(v.z + b.z, 0.f);
            v.w = fmaxf(v.w + b.w, 0.f);
        }
        float* p = xs + r * XSS + c;
        p[0] = v.x; p[1] = v.y; p[2] = v.z; p[3] = v.w;
    }
    __syncthreads();

    const int tx = tid % TX, ty = tid / TX;
    const int r0 = ty * 8,   c0 = tx * 8;

    float acc[8][8];
#pragma unroll
    for (int i = 0; i < 8; i++)
#pragma unroll
        for (int j = 0; j < 8; j++) acc[i][j] = 0.f;

#pragma unroll 2
    for (int k = 0; k < KDIM; k++) {
        float a[8], b[8];
#pragma unroll
        for (int i = 0; i < 8; i++) a[i] = xs[(r0 + i) * XSS + k];
#pragma unroll
        for (int j = 0; j < 8; j++) b[j] = ws[k * NC + c0 + j];
#pragma unroll
        for (int i = 0; i < 8; i++)
#pragma unroll
            for (int j = 0; j < 8; j++) acc[i][j] += a[i] * b[j];
    }

#pragma unroll
    for (int i = 0; i < 8; i++) {
        int gr = row0 + r0 + i;
        if (gr < NN) {
            float4 v0 = make_float4(acc[i][0], acc[i][1], acc[i][2], acc[i][3]);
            float4 v1 = make_float4(acc[i][4], acc[i][5], acc[i][6], acc[i][7]);
            *(float4*)(C + (size_t)gr * NC + c0 + 0) = v0;
            *(float4*)(C + (size_t)gr * NC + c0 + 4) = v1;
        }
    }
}

// ---------------- self-loop init + edge scatter ------------------------------
// agg1[i,:] = dinv[i]^2 * h1[i,:]
__global__ void k_self1() {
    int i = blockIdx.x * blockDim.x + threadIdx.x;  // float4 index
    if (i >= NN * (HID / 4)) return;
    int node = i >> 5;                              // i / 32
    float d = g_dinv[node]; float w = d * d;
    float4 v = *((const float4*)g_h1 + i);
    v.x *= w; v.y *= w; v.z *= w; v.w *= w;
    *((float4*)g_agg1 + i) = v;
}

// out[i,:] = dinv[i]^2 * h2[i,:] + b2   (then scatter2 accumulates on top)
__global__ void k_self2(const float* __restrict__ b2, float* __restrict__ out) {
    int i = blockIdx.x * blockDim.x + threadIdx.x;  // float4 index
    if (i >= NN * (OUTD / 4)) return;
    int node = i >> 4;                              // i / 16
    int c    = (i & 15) * 4;
    float d = g_dinv[node]; float w = d * d;
    float4 v = *((const float4*)g_h2 + i);
    float4 b = *(const float4*)(b2 + c);
    v.x = v.x * w + b.x; v.y = v.y * w + b.y;
    v.z = v.z * w + b.z; v.w = v.w * w + b.w;
    *((float4*)out + i) = v;
}

// One thread per (edge, float4 chunk); chunk is the fast index so a warp maps
// to one edge (D=128) -> uniform src/tgt/dinv loads, coalesced gather/atomics.
template<int D>
__global__ void k_scatter(const int* __restrict__ src, const int* __restrict__ tgt,
                          const float* __restrict__ h, float* __restrict__ agg) {
    constexpr int CH = D / 4;
    unsigned idx = blockIdx.x * blockDim.x + threadIdx.x;
    if (idx >= (unsigned)NE * CH) return;
    int e = idx / CH;
    int c = idx % CH;
    int s = src[e], t = tgt[e];
    float w = g_dinv[s] * g_dinv[t];
    float4 v = *(const float4*)(h + (size_t)s * D + c * 4);
    float* o = agg + (size_t)t * D + c * 4;
    atomicAdd(o + 0, w * v.x);
    atomicAdd(o + 1, w * v.y);
    atomicAdd(o + 2, w * v.z);
    atomicAdd(o + 3, w * v.w);
}

// ---------------- launcher ----------------------------------------------------
extern "C" void kernel_launch(void* const* d_in, const int* in_sizes, int n_in,
                              void* d_out, int out_size) {
    const float* x  = (const float*)d_in[0];
    const int*   ei = (const int*)  d_in[1];
    const float* W1 = (const float*)d_in[2];
    const float* b1 = (const float*)d_in[3];
    const float* W2 = (const float*)d_in[4];
    const float* b2 = (const float*)d_in[5];
    float* out = (float*)d_out;

    const int* src = ei;         // edge_index[0]
    const int* tgt = ei + NE;    // edge_index[1]

    void *p_h1, *p_agg1, *p_h2;
    cudaGetSymbolAddress(&p_h1,   g_h1);
    cudaGetSymbolAddress(&p_agg1, g_agg1);
    cudaGetSymbolAddress(&p_h2,   g_h2);
    float* h1   = (float*)p_h1;
    float* agg1 = (float*)p_agg1;
    float* h2   = (float*)p_h2;

    // dynamic smem sizes
    const int smem1 = (128 * (KDIM + 1) + KDIM * 128) * (int)sizeof(float); // ~128.5KB
    const int smem2 = (256 * (KDIM + 1) + KDIM * 64)  * (int)sizeof(float); // ~161KB
    cudaFuncSetAttribute(k_gemm<128, false>, cudaFuncAttributeMaxDynamicSharedMemorySize, smem1);
    cudaFuncSetAttribute(k_gemm<64,  true>,  cudaFuncAttributeMaxDynamicSharedMemorySize, smem2);

    // normalization
    k_init_deg<<<(NN + 255) / 256, 256>>>();
    k_deg     <<<(NE + 255) / 256, 256>>>(tgt);
    k_dinv    <<<(NN + 255) / 256, 256>>>();

    // layer 1: h1 = x @ W1 ; agg1 = scatter(norm * h1) + self
    k_gemm<128, false><<<(NN + 127) / 128, 256, smem1>>>(x, W1, nullptr, h1);
    k_self1<<<(NN * 32 + 255) / 256, 256>>>();
    k_scatter<128><<<(NE * 32 + 255) / 256, 256>>>(src, tgt, h1, agg1);

    // layer 2: h2 = relu(agg1 + b1) @ W2 ; out = scatter(norm * h2) + self + b2
    k_gemm<64, true><<<(NN + 255) / 256, 256, smem2>>>(agg1, W2, b1, h2);
    k_self2<<<(NN * 16 + 255) / 256, 256>>>(b2, out);
    k_scatter<64><<<(NE * 16 + 255) / 256, 256>>>(src, tgt, h2, out);
}

// round 3
// speedup vs baseline: 1.6986x; 1.6986x over previous
#include <cuda_runtime.h>
#include <math.h>

// Problem constants (fixed by the reference)
#define NN 100000
#define NE 1600000
static constexpr int KDIM = 128;   // IN_DIM == HID_DIM == 128
static constexpr int HID  = 128;
static constexpr int OUTD = 64;

// ---------------- device scratch (allocation-free rule: __device__ globals) ---
__device__ float g_deg [NN];
__device__ float g_dinv[NN];
__device__ float g_h1  [(size_t)NN * HID];   // x @ W1
__device__ float g_agg1[(size_t)NN * HID];   // aggregated layer-1 (pre bias/relu)
__device__ float g_h2  [(size_t)NN * OUTD];  // relu(agg1+b1) @ W2

// ---------------- degree / normalization ------------------------------------
__global__ void k_init_deg() {
    int i = blockIdx.x * blockDim.x + threadIdx.x;
    if (i < NN) g_deg[i] = 1.0f;  // self-loop contributes 1
}

__global__ void k_deg(const int* __restrict__ tgt) {
    int e = blockIdx.x * blockDim.x + threadIdx.x;
    if (e < NE) atomicAdd(&g_deg[tgt[e]], 1.0f);
}

__global__ void k_dinv() {
    int i = blockIdx.x * blockDim.x + threadIdx.x;
    if (i < NN) g_dinv[i] = rsqrtf(g_deg[i]);
}

// ---------------- GEMM: 128 threads/CTA, 8x8 micro-tile, 2 CTAs/SM ----------
// NC=128 -> TX=16, TY=8,  BM=64   (smem ~98.5KB)
// NC=64  -> TX=8,  TY=16, BM=128  (smem ~98.6KB)
// FUSE: apply x <- max(x + bias[k], 0) to the A-tile on load (layer-2 input).
template<int NC, bool FUSE>
__global__ void __launch_bounds__(128, 2)
k_gemm(const float* __restrict__ A, const float* __restrict__ W,
       const float* __restrict__ bin, float* __restrict__ C) {
    constexpr int TPB = 128;
    constexpr int TX  = NC / 8;       // thread cols
    constexpr int TY  = TPB / TX;     // thread rows
    constexpr int BM  = TY * 8;       // rows per block
    constexpr int XSS = KDIM + 1;     // padded stride (129) to dodge bank conflicts

    extern __shared__ float sm[];
    float* xs = sm;                   // BM * XSS
    float* ws = sm + BM * XSS;        // KDIM * NC

    const int tid  = threadIdx.x;
    const int row0 = blockIdx.x * BM;

    // load W (KDIM x NC), row-major, vectorized
    for (int i = tid * 4; i < KDIM * NC; i += TPB * 4) {
        float4 v = *(const float4*)(W + i);
        ws[i + 0] = v.x; ws[i + 1] = v.y; ws[i + 2] = v.z; ws[i + 3] = v.w;
    }
    // load A tile (BM x KDIM), zero-padded past NN
    for (int i = tid * 4; i < BM * KDIM; i += TPB * 4) {
        int r = i / KDIM, c = i % KDIM;
        int gr = row0 + r;
        float4 v = make_float4(0.f, 0.f, 0.f, 0.f);
        if (gr < NN) v = *(const float4*)(A + (size_t)gr * KDIM + c);
        if (FUSE) {
            float4 b = *(const float4*)(bin + c);
            v.x = fmaxf(v.x + b.x, 0.f);
            v.y = fmaxf(v.y + b.y, 0.f);
            v.z = fmaxf(v.z + b.z, 0.f);
            v.w = fmaxf(v.w + b.w, 0.f);
        }
        float* p = xs + r * XSS + c;
        p[0] = v.x; p[1] = v.y; p[2] = v.z; p[3] = v.w;
    }
    __syncthreads();

    const int tx = tid % TX, ty = tid / TX;
    const int r0 = ty * 8,   c0 = tx * 8;

    float acc[8][8];
#pragma unroll
    for (int i = 0; i < 8; i++)
#pragma unroll
        for (int j = 0; j < 8; j++) acc[i][j] = 0.f;

#pragma unroll 4
    for (int k = 0; k < KDIM; k++) {
        float a[8], b[8];
#pragma unroll
        for (int i = 0; i < 8; i++) a[i] = xs[(r0 + i) * XSS + k];
#pragma unroll
        for (int j = 0; j < 8; j++) b[j] = ws[k * NC + c0 + j];
#pragma unroll
        for (int i = 0; i < 8; i++)
#pragma unroll
            for (int j = 0; j < 8; j++) acc[i][j] += a[i] * b[j];
    }

#pragma unroll
    for (int i = 0; i < 8; i++) {
        int gr = row0 + r0 + i;
        if (gr < NN) {
            float4 v0 = make_float4(acc[i][0], acc[i][1], acc[i][2], acc[i][3]);
            float4 v1 = make_float4(acc[i][4], acc[i][5], acc[i][6], acc[i][7]);
            *(float4*)(C + (size_t)gr * NC + c0 + 0) = v0;
            *(float4*)(C + (size_t)gr * NC + c0 + 4) = v1;
        }
    }
}

// ---------------- self-loop init + edge scatter ------------------------------
// agg1[i,:] = dinv[i]^2 * h1[i,:]
__global__ void k_self1() {
    int i = blockIdx.x * blockDim.x + threadIdx.x;  // float4 index
    if (i >= NN * (HID / 4)) return;
    int node = i >> 5;                              // i / 32
    float d = g_dinv[node]; float w = d * d;
    float4 v = *((const float4*)g_h1 + i);
    v.x *= w; v.y *= w; v.z *= w; v.w *= w;
    *((float4*)g_agg1 + i) = v;
}

// out[i,:] = dinv[i]^2 * h2[i,:] + b2   (then scatter2 accumulates on top)
__global__ void k_self2(const float* __restrict__ b2, float* __restrict__ out) {
    int i = blockIdx.x * blockDim.x + threadIdx.x;  // float4 index
    if (i >= NN * (OUTD / 4)) return;
    int node = i >> 4;                              // i / 16
    int c    = (i & 15) * 4;
    float d = g_dinv[node]; float w = d * d;
    float4 v = *((const float4*)g_h2 + i);
    float4 b = *(const float4*)(b2 + c);
    v.x = v.x * w + b.x; v.y = v.y * w + b.y;
    v.z = v.z * w + b.z; v.w = v.w * w + b.w;
    *((float4*)out + i) = v;
}

// Vectorized 16B reduction: 1 L2 atomic op instead of 4 (sm_90+)
__device__ __forceinline__ void red_add_v4(float* p, float a, float b, float c, float d) {
#if __CUDA_ARCH__ >= 900
    asm volatile("red.global.add.v4.f32 [%0], {%1, %2, %3, %4};"
                 :: "l"(p), "f"(a), "f"(b), "f"(c), "f"(d) : "memory");
#else
    atomicAdd(p + 0, a); atomicAdd(p + 1, b);
    atomicAdd(p + 2, c); atomicAdd(p + 3, d);
#endif
}

// One thread per (edge, float4 chunk); chunk is the fast index so a warp maps
// to one edge (D=128) -> uniform src/tgt/dinv loads, coalesced gather/atomics.
template<int D>
__global__ void __launch_bounds__(256)
k_scatter(const int* __restrict__ src, const int* __restrict__ tgt,
          const float* __restrict__ h, float* __restrict__ agg) {
    constexpr int CH = D / 4;
    unsigned idx = blockIdx.x * blockDim.x + threadIdx.x;
    if (idx >= (unsigned)NE * CH) return;
    int e = idx / CH;
    int c = idx % CH;
    int s = src[e], t = tgt[e];
    float w = g_dinv[s] * g_dinv[t];
    float4 v = *(const float4*)(h + (size_t)s * D + c * 4);
    float* o = agg + (size_t)t * D + c * 4;
    red_add_v4(o, w * v.x, w * v.y, w * v.z, w * v.w);
}

// ---------------- launcher ----------------------------------------------------
extern "C" void kernel_launch(void* const* d_in, const int* in_sizes, int n_in,
                              void* d_out, int out_size) {
    const float* x  = (const float*)d_in[0];
    const int*   ei = (const int*)  d_in[1];
    const float* W1 = (const float*)d_in[2];
    const float* b1 = (const float*)d_in[3];
    const float* W2 = (const float*)d_in[4];
    const float* b2 = (const float*)d_in[5];
    float* out = (float*)d_out;

    const int* src = ei;         // edge_index[0]
    const int* tgt = ei + NE;    // edge_index[1]

    void *p_h1, *p_agg1, *p_h2;
    cudaGetSymbolAddress(&p_h1,   g_h1);
    cudaGetSymbolAddress(&p_agg1, g_agg1);
    cudaGetSymbolAddress(&p_h2,   g_h2);
    float* h1   = (float*)p_h1;
    float* agg1 = (float*)p_agg1;
    float* h2   = (float*)p_h2;

    // dynamic smem sizes (both ~98.5KB -> 2 CTAs/SM within 228KB)
    const int smem1 = (64  * (KDIM + 1) + KDIM * 128) * (int)sizeof(float);
    const int smem2 = (128 * (KDIM + 1) + KDIM * 64)  * (int)sizeof(float);
    cudaFuncSetAttribute(k_gemm<128, false>, cudaFuncAttributeMaxDynamicSharedMemorySize, smem1);
    cudaFuncSetAttribute(k_gemm<64,  true>,  cudaFuncAttributeMaxDynamicSharedMemorySize, smem2);

    // normalization
    k_init_deg<<<(NN + 255) / 256, 256>>>();
    k_deg     <<<(NE + 255) / 256, 256>>>(tgt);
    k_dinv    <<<(NN + 255) / 256, 256>>>();

    // layer 1: h1 = x @ W1 ; agg1 = scatter(norm * h1) + self
    k_gemm<128, false><<<(NN + 63) / 64, 128, smem1>>>(x, W1, nullptr, h1);
    k_self1<<<(NN * 32 + 255) / 256, 256>>>();
    k_scatter<128><<<(NE * 32 + 255) / 256, 256>>>(src, tgt, h1, agg1);

    // layer 2: h2 = relu(agg1 + b1) @ W2 ; out = scatter(norm * h2) + self + b2
    k_gemm<64, true><<<(NN + 127) / 128, 128, smem2>>>(agg1, W2, b1, h2);
    k_self2<<<(NN * 16 + 255) / 256, 256>>>(b2, out);
    k_scatter<64><<<(NE * 16 + 255) / 256, 256>>>(src, tgt, h2, out);
}

// round 5
// speedup vs baseline: 1.7591x; 1.0356x over previous
#include <cuda_runtime.h>
#include <math.h>

// Problem constants (fixed by the reference)
#define NN 100000
#define NE 1600000
static constexpr int KDIM = 128;   // IN_DIM == HID_DIM == 128
static constexpr int HID  = 128;
static constexpr int OUTD = 64;

// ---------------- device scratch (allocation-free rule: __device__ globals) ---
__device__ float g_deg [NN];
__device__ float g_dinv[NN];
__device__ float g_h1  [(size_t)NN * HID];   // x @ W1
__device__ float g_agg1[(size_t)NN * HID];   // aggregated layer-1 (pre bias/relu)
__device__ float g_h2  [(size_t)NN * OUTD];  // relu(agg1+b1) @ W2

// ---------------- degree / normalization ------------------------------------
__global__ void k_init_deg() {
    int i = blockIdx.x * blockDim.x + threadIdx.x;
    if (i < NN) g_deg[i] = 1.0f;  // self-loop contributes 1
}

__global__ void k_deg(const int* __restrict__ tgt) {
    int e = blockIdx.x * blockDim.x + threadIdx.x;
    if (e < NE) atomicAdd(&g_deg[tgt[e]], 1.0f);
}

__global__ void k_dinv() {
    int i = blockIdx.x * blockDim.x + threadIdx.x;
    if (i < NN) g_dinv[i] = rsqrtf(g_deg[i]);
}

// ---------------- tf32 helpers -----------------------------------------------
__device__ __forceinline__ unsigned f2tf32(float x) {
    unsigned r; asm("cvt.rna.tf32.f32 %0, %1;" : "=r"(r) : "f"(x)); return r;
}

#define MMA_TF32(c, a, b)                                                     \
    asm volatile(                                                             \
        "mma.sync.aligned.m16n8k8.row.col.f32.tf32.tf32.f32 "                 \
        "{%0,%1,%2,%3}, {%4,%5,%6,%7}, {%8,%9}, {%0,%1,%2,%3};"               \
        : "+f"((c)[0]), "+f"((c)[1]), "+f"((c)[2]), "+f"((c)[3])              \
        : "r"((a)[0]), "r"((a)[1]), "r"((a)[2]), "r"((a)[3]),                 \
          "r"((b)[0]), "r"((b)[1]))

// ---------------- 3xTF32 tensor-core GEMM ------------------------------------
// CTA: 256 threads = 8 warps in a 4(m) x 2(n) grid. CTA tile 128 x BN.
// Warp tile: 32 x (BN/2). K=128 fully staged in smem.
// 3xTF32: acc += ah*bh + ah*bl + al*bh  (fp32-grade accuracy, ~1e-7)
// Epilogue fuses the self-loop term: H = result, AGG = dinv^2 * result (+b2).
// FUSE: A-tile gets relu(x + bin) on load (layer-2 input path).
template<int BN, bool FUSE, bool ADDB2>
__global__ void __launch_bounds__(256)
k_gemm_tc(const float* __restrict__ A, const float* __restrict__ W,
          const float* __restrict__ bin, float* __restrict__ H,
          float* __restrict__ AGG, const float* __restrict__ b2) {
    constexpr int BM  = 128;
    constexpr int XSS = KDIM + 4;   // 132: (4*row+k)%32 distinct -> conflict-free A frags
    constexpr int NS  = BN + 8;     // 136/72: (8*k+n)%32 distinct -> conflict-free B frags
    constexpr int WN  = BN / 2;     // warp n-tile: 64 / 32
    constexpr int NF  = WN / 8;     // n-frags: 8 / 4
    constexpr int MF  = 2;          // m-frags (warp m-tile 32)

    extern __shared__ float sm[];
    float* xs = sm;                  // BM * XSS
    float* ws = sm + BM * XSS;       // KDIM * NS

    const int tid  = threadIdx.x;
    const int row0 = blockIdx.x * BM;

    // stage W (KDIM x BN) with padded stride NS
    for (int i = tid * 4; i < KDIM * BN; i += 256 * 4) {
        int k = i / BN, n = i % BN;
        float4 v = *(const float4*)(W + i);
        float* p = ws + k * NS + n;
        p[0] = v.x; p[1] = v.y; p[2] = v.z; p[3] = v.w;
    }
    // stage A tile (BM x KDIM), zero-padded past NN, optional bias+relu
    for (int i = tid * 4; i < BM * KDIM; i += 256 * 4) {
        int r = i / KDIM, c = i % KDIM;
        int gr = row0 + r;
        float4 v = make_float4(0.f, 0.f, 0.f, 0.f);
        if (gr < NN) v = *(const float4*)(A + (size_t)gr * KDIM + c);
        if (FUSE) {
            float4 b = *(const float4*)(bin + c);
            v.x = fmaxf(v.x + b.x, 0.f);
            v.y = fmaxf(v.y + b.y, 0.f);
            v.z = fmaxf(v.z + b.z, 0.f);
            v.w = fmaxf(v.w + b.w, 0.f);
        }
        float* p = xs + r * XSS + c;
        p[0] = v.x; p[1] = v.y; p[2] = v.z; p[3] = v.w;
    }
    __syncthreads();

    const int w    = tid >> 5, lane = tid & 31;
    const int wm   = w & 3,    wn   = w >> 2;
    const int m0   = wm * 32,  n0   = wn * WN;
    const int grp  = lane >> 2, q   = lane & 3;

    float acc[MF][NF][4];
#pragma unroll
    for (int i = 0; i < MF; i++)
#pragma unroll
        for (int j = 0; j < NF; j++)
#pragma unroll
            for (int t = 0; t < 4; t++) acc[i][j][t] = 0.f;

#pragma unroll 2
    for (int k0 = 0; k0 < KDIM; k0 += 8) {
        unsigned ah[MF][4], al[MF][4];
#pragma unroll
        for (int mf = 0; mf < MF; mf++) {
            int r = m0 + mf * 16 + grp;
            float x0 = xs[r * XSS + k0 + q];
            float x1 = xs[(r + 8) * XSS + k0 + q];
            float x2 = xs[r * XSS + k0 + q + 4];
            float x3 = xs[(r + 8) * XSS + k0 + q + 4];
            ah[mf][0] = f2tf32(x0); al[mf][0] = f2tf32(x0 - __uint_as_float(ah[mf][0]));
            ah[mf][1] = f2tf32(x1); al[mf][1] = f2tf32(x1 - __uint_as_float(ah[mf][1]));
            ah[mf][2] = f2tf32(x2); al[mf][2] = f2tf32(x2 - __uint_as_float(ah[mf][2]));
            ah[mf][3] = f2tf32(x3); al[mf][3] = f2tf32(x3 - __uint_as_float(ah[mf][3]));
        }
        unsigned bh[NF][2], bl[NF][2];
#pragma unroll
        for (int nf = 0; nf < NF; nf++) {
            int n = n0 + nf * 8 + grp;
            float y0 = ws[(k0 + q) * NS + n];
            float y1 = ws[(k0 + q + 4) * NS + n];
            bh[nf][0] = f2tf32(y0); bl[nf][0] = f2tf32(y0 - __uint_as_float(bh[nf][0]));
            bh[nf][1] = f2tf32(y1); bl[nf][1] = f2tf32(y1 - __uint_as_float(bh[nf][1]));
        }
#pragma unroll
        for (int mf = 0; mf < MF; mf++)
#pragma unroll
            for (int nf = 0; nf < NF; nf++) {
                MMA_TF32(acc[mf][nf], ah[mf], bh[nf]);
                MMA_TF32(acc[mf][nf], ah[mf], bl[nf]);
                MMA_TF32(acc[mf][nf], al[mf], bh[nf]);
            }
    }

    // epilogue: H = acc, AGG = dinv^2 * acc (+ b2)
#pragma unroll
    for (int mf = 0; mf < MF; mf++) {
        int r1 = row0 + m0 + mf * 16 + grp;
        int r2 = r1 + 8;
        float w1 = 0.f, w2 = 0.f;
        if (r1 < NN) { float d = g_dinv[r1]; w1 = d * d; }
        if (r2 < NN) { float d = g_dinv[r2]; w2 = d * d; }
#pragma unroll
        for (int nf = 0; nf < NF; nf++) {
            int col = n0 + nf * 8 + 2 * q;
            float bx = 0.f, by = 0.f;
            if (ADDB2) { bx = b2[col]; by = b2[col + 1]; }
            if (r1 < NN) {
                float2 h = make_float2(acc[mf][nf][0], acc[mf][nf][1]);
                *(float2*)(H   + (size_t)r1 * BN + col) = h;
                *(float2*)(AGG + (size_t)r1 * BN + col) =
                    make_float2(w1 * h.x + bx, w1 * h.y + by);
            }
            if (r2 < NN) {
                float2 h = make_float2(acc[mf][nf][2], acc[mf][nf][3]);
                *(float2*)(H   + (size_t)r2 * BN + col) = h;
                *(float2*)(AGG + (size_t)r2 * BN + col) =
                    make_float2(w2 * h.x + bx, w2 * h.y + by);
            }
        }
    }
}

// ---------------- edge scatter ------------------------------------------------
// Vectorized 16B reduction: 1 L2 atomic op instead of 4 (sm_90+)
__device__ __forceinline__ void red_add_v4(float* p, float a, float b, float c, float d) {
    asm volatile("red.global.add.v4.f32 [%0], {%1, %2, %3, %4};"
                 :: "l"(p), "f"(a), "f"(b), "f"(c), "f"(d) : "memory");
}

// One thread per (edge, float4 chunk); chunk is the fast index so a warp maps
// to one edge (D=128) -> uniform src/tgt/dinv loads, coalesced gather/atomics.
template<int D>
__global__ void __launch_bounds__(256)
k_scatter(const int* __restrict__ src, const int* __restrict__ tgt,
          const float* __restrict__ h, float* __restrict__ agg) {
    constexpr int CH = D / 4;
    unsigned idx = blockIdx.x * blockDim.x + threadIdx.x;
    if (idx >= (unsigned)NE * CH) return;
    int e = idx / CH;
    int c = idx % CH;
    int s = src[e], t = tgt[e];
    float w = g_dinv[s] * g_dinv[t];
    float4 v = *(const float4*)(h + (size_t)s * D + c * 4);
    float* o = agg + (size_t)t * D + c * 4;
    red_add_v4(o, w * v.x, w * v.y, w * v.z, w * v.w);
}

// ---------------- launcher ----------------------------------------------------
extern "C" void kernel_launch(void* const* d_in, const int* in_sizes, int n_in,
                              void* d_out, int out_size) {
    const float* x  = (const float*)d_in[0];
    const int*   ei = (const int*)  d_in[1];
    const float* W1 = (const float*)d_in[2];
    const float* b1 = (const float*)d_in[3];
    const float* W2 = (const float*)d_in[4];
    const float* b2 = (const float*)d_in[5];
    float* out = (float*)d_out;

    const int* src = ei;         // edge_index[0]
    const int* tgt = ei + NE;    // edge_index[1]

    void *p_h1, *p_agg1, *p_h2;
    cudaGetSymbolAddress(&p_h1,   g_h1);
    cudaGetSymbolAddress(&p_agg1, g_agg1);
    cudaGetSymbolAddress(&p_h2,   g_h2);
    float* h1   = (float*)p_h1;
    float* agg1 = (float*)p_agg1;
    float* h2   = (float*)p_h2;

    const int smem1 = (128 * (KDIM + 4) + KDIM * (128 + 8)) * (int)sizeof(float); // 137216
    const int smem2 = (128 * (KDIM + 4) + KDIM * (64  + 8)) * (int)sizeof(float); // 104448
    cudaFuncSetAttribute((const void*)k_gemm_tc<128, false, false>,
                         cudaFuncAttributeMaxDynamicSharedMemorySize, smem1);
    cudaFuncSetAttribute((const void*)k_gemm_tc<64, true, true>,
                         cudaFuncAttributeMaxDynamicSharedMemorySize, smem2);

    // normalization (dinv needed by gemm epilogues)
    k_init_deg<<<(NN + 255) / 256, 256>>>();
    k_deg     <<<(NE + 255) / 256, 256>>>(tgt);
    k_dinv    <<<(NN + 255) / 256, 256>>>();

    // layer 1: h1 = x @ W1 ; agg1 = dinv^2*h1 (fused) ; += edge scatter
    k_gemm_tc<128, false, false><<<(NN + 127) / 128, 256, smem1>>>(
        x, W1, nullptr, h1, agg1, nullptr);
    k_scatter<128><<<(NE * 32 + 255) / 256, 256>>>(src, tgt, h1, agg1);

    // layer 2: h2 = relu(agg1+b1) @ W2 ; out = dinv^2*h2 + b2 (fused) ; += scatter
    k_gemm_tc<64, true, true><<<(NN + 127) / 128, 256, smem2>>>(
        agg1, W2, b1, h2, out, b2);
    k_scatter<64><<<(NE * 16 + 255) / 256, 256>>>(src, tgt, h2, out);
}

// round 7
// speedup vs baseline: 3.0406x; 1.7284x over previous
#include <cuda_runtime.h>
#include <math.h>

// Problem constants (fixed by the reference)
#define NN 100000
#define NE 1600000
static constexpr int KDIM = 128;
static constexpr int HID  = 128;
static constexpr int OUTD = 64;
static constexpr int NB_SCAN = (NN + 1023) / 1024;   // 98 blocks of 1024 items

// ---------------- device scratch ---------------------------------------------
__device__ float g_deg [NN];
__device__ float g_dinv[NN];
__device__ int   g_rowptr[NN];
__device__ int   g_cursor[NN];
__device__ int   g_part[128];                 // scan spine partials
__device__ int   g_eidx[NE];                  // CSR column (src) indices
__device__ float g_h1  [(size_t)NN * HID];
__device__ float g_agg1[(size_t)NN * HID];
__device__ float g_h2  [(size_t)NN * OUTD];

// ---------------- degree / normalization -------------------------------------
__global__ void k_init_deg() {
    int i = blockIdx.x * blockDim.x + threadIdx.x;
    if (i < NN) g_deg[i] = 1.0f;  // self-loop contributes 1
}
__global__ void k_deg(const int* __restrict__ tgt) {
    int e = blockIdx.x * blockDim.x + threadIdx.x;
    if (e < NE) atomicAdd(&g_deg[tgt[e]], 1.0f);
}
__global__ void k_dinv() {
    int i = blockIdx.x * blockDim.x + threadIdx.x;
    if (i < NN) g_dinv[i] = rsqrtf(g_deg[i]);
}

// ---------------- CSR build: scan of per-node in-edge counts ------------------
// counts[i] = (int)deg[i] - 1. 3-phase exclusive scan + cursor fill.
__global__ void k_scan_block() {            // 256 thr, 4 items/thr = 1024/block
    __shared__ int sd[256];
    int tid  = threadIdx.x;
    int base = blockIdx.x * 1024 + tid * 4;
    int v[4], s = 0;
#pragma unroll
    for (int j = 0; j < 4; j++) {
        int i = base + j;
        int c = (i < NN) ? (int)g_deg[i] - 1 : 0;
        v[j] = s; s += c;
    }
    sd[tid] = s; __syncthreads();
    for (int off = 1; off < 256; off <<= 1) {
        int t = (tid >= off) ? sd[tid - off] : 0;
        __syncthreads(); sd[tid] += t; __syncthreads();
    }
    int excl = sd[tid] - s;
#pragma unroll
    for (int j = 0; j < 4; j++) {
        int i = base + j;
        if (i < NN) g_rowptr[i] = excl + v[j];
    }
    if (tid == 255) g_part[blockIdx.x] = sd[255];
}

__global__ void k_scan_spine() {            // 1 block, 128 threads
    __shared__ int sp[128];
    int tid = threadIdx.x;
    int v = (tid < NB_SCAN) ? g_part[tid] : 0;
    sp[tid] = v; __syncthreads();
    for (int off = 1; off < 128; off <<= 1) {
        int t = (tid >= off) ? sp[tid - off] : 0;
        __syncthreads(); sp[tid] += t; __syncthreads();
    }
    g_part[tid] = sp[tid] - v;              // exclusive
}

__global__ void k_scan_add() {
    int i = blockIdx.x * blockDim.x + threadIdx.x;
    if (i < NN) {
        g_rowptr[i] += g_part[i >> 10];
        g_cursor[i] = 0;
    }
}

__global__ void k_fill(const int* __restrict__ src, const int* __restrict__ tgt) {
    int e = blockIdx.x * blockDim.x + threadIdx.x;
    if (e >= NE) return;
    int t = tgt[e];
    int pos = g_rowptr[t] + atomicAdd(&g_cursor[t], 1);
    g_eidx[pos] = src[e];
}

// ---------------- tf32 helpers -----------------------------------------------
__device__ __forceinline__ unsigned f2tf32(float x) {
    unsigned r; asm("cvt.rna.tf32.f32 %0, %1;" : "=r"(r) : "f"(x)); return r;
}
#define MMA_TF32(c, a, b)                                                     \
    asm volatile(                                                             \
        "mma.sync.aligned.m16n8k8.row.col.f32.tf32.tf32.f32 "                 \
        "{%0,%1,%2,%3}, {%4,%5,%6,%7}, {%8,%9}, {%0,%1,%2,%3};"               \
        : "+f"((c)[0]), "+f"((c)[1]), "+f"((c)[2]), "+f"((c)[3])              \
        : "r"((a)[0]), "r"((a)[1]), "r"((a)[2]), "r"((a)[3]),                 \
          "r"((b)[0]), "r"((b)[1]))

// ---------------- 3xTF32 tensor-core GEMM, 512 threads (16 warps/SM) ---------
// CTA tile 256 x BN; warp grid WMC(m) x WNC(n); warp tile (MF*16) x (NF*8).
// GEMM1: BN=128, 4x4 warps, MF=4, NF=4.   GEMM2: BN=64, 8x2 warps, MF=2, NF=4.
// FUSE: A-tile gets relu(x + bin) on load.
template<int BN, int WMC, int MF, int NF, bool FUSE>
__global__ void __launch_bounds__(512)
k_gemm_tc(const float* __restrict__ A, const float* __restrict__ W,
          const float* __restrict__ bin, float* __restrict__ H) {
    constexpr int BM  = 256;
    constexpr int XSS = KDIM + 4;   // 132: conflict-free A frag LDS
    constexpr int NS  = BN + 8;     // conflict-free B frag LDS

    extern __shared__ float sm[];
    float* xs = sm;                  // BM * XSS
    float* ws = sm + BM * XSS;       // KDIM * NS

    const int tid  = threadIdx.x;
    const int row0 = blockIdx.x * BM;

    for (int i = tid * 4; i < KDIM * BN; i += 512 * 4) {
        int k = i / BN, n = i % BN;
        float4 v = *(const float4*)(W + i);
        float* p = ws + k * NS + n;
        p[0] = v.x; p[1] = v.y; p[2] = v.z; p[3] = v.w;
    }
    for (int i = tid * 4; i < BM * KDIM; i += 512 * 4) {
        int r = i / KDIM, c = i % KDIM;
        int gr = row0 + r;
        float4 v = make_float4(0.f, 0.f, 0.f, 0.f);
        if (gr < NN) v = *(const float4*)(A + (size_t)gr * KDIM + c);
        if (FUSE) {
            float4 b = *(const float4*)(bin + c);
            v.x = fmaxf(v.x + b.x, 0.f);
            v.y = fmaxf(v.y + b.y, 0.f);
            v.z = fmaxf(v.z + b.z, 0.f);
            v.w = fmaxf(v.w + b.w, 0.f);
        }
        float* p = xs + r * XSS + c;
        p[0] = v.x; p[1] = v.y; p[2] = v.z; p[3] = v.w;
    }
    __syncthreads();

    const int w    = tid >> 5, lane = tid & 31;
    const int wm   = w % WMC,  wn   = w / WMC;
    const int m0   = wm * (MF * 16), n0 = wn * (NF * 8);
    const int grp  = lane >> 2, q   = lane & 3;

    float acc[MF][NF][4];
#pragma unroll
    for (int i = 0; i < MF; i++)
#pragma unroll
        for (int j = 0; j < NF; j++)
#pragma unroll
            for (int t = 0; t < 4; t++) acc[i][j][t] = 0.f;

#pragma unroll 2
    for (int k0 = 0; k0 < KDIM; k0 += 8) {
        unsigned ah[MF][4], al[MF][4];
#pragma unroll
        for (int mf = 0; mf < MF; mf++) {
            int r = m0 + mf * 16 + grp;
            float x0 = xs[r * XSS + k0 + q];
            float x1 = xs[(r + 8) * XSS + k0 + q];
            float x2 = xs[r * XSS + k0 + q + 4];
            float x3 = xs[(r + 8) * XSS + k0 + q + 4];
            ah[mf][0] = f2tf32(x0); al[mf][0] = f2tf32(x0 - __uint_as_float(ah[mf][0]));
            ah[mf][1] = f2tf32(x1); al[mf][1] = f2tf32(x1 - __uint_as_float(ah[mf][1]));
            ah[mf][2] = f2tf32(x2); al[mf][2] = f2tf32(x2 - __uint_as_float(ah[mf][2]));
            ah[mf][3] = f2tf32(x3); al[mf][3] = f2tf32(x3 - __uint_as_float(ah[mf][3]));
        }
        unsigned bh[NF][2], bl[NF][2];
#pragma unroll
        for (int nf = 0; nf < NF; nf++) {
            int n = n0 + nf * 8 + grp;
            float y0 = ws[(k0 + q) * NS + n];
            float y1 = ws[(k0 + q + 4) * NS + n];
            bh[nf][0] = f2tf32(y0); bl[nf][0] = f2tf32(y0 - __uint_as_float(bh[nf][0]));
            bh[nf][1] = f2tf32(y1); bl[nf][1] = f2tf32(y1 - __uint_as_float(bh[nf][1]));
        }
#pragma unroll
        for (int mf = 0; mf < MF; mf++)
#pragma unroll
            for (int nf = 0; nf < NF; nf++) {
                MMA_TF32(acc[mf][nf], ah[mf], bh[nf]);
                MMA_TF32(acc[mf][nf], ah[mf], bl[nf]);
                MMA_TF32(acc[mf][nf], al[mf], bh[nf]);
            }
    }

#pragma unroll
    for (int mf = 0; mf < MF; mf++) {
        int r1 = row0 + m0 + mf * 16 + grp;
        int r2 = r1 + 8;
#pragma unroll
        for (int nf = 0; nf < NF; nf++) {
            int col = n0 + nf * 8 + 2 * q;
            if (r1 < NN)
                *(float2*)(H + (size_t)r1 * BN + col) =
                    make_float2(acc[mf][nf][0], acc[mf][nf][1]);
            if (r2 < NN)
                *(float2*)(H + (size_t)r2 * BN + col) =
                    make_float2(acc[mf][nf][2], acc[mf][nf][3]);
        }
    }
}

// ---------------- CSR aggregation: warp per target node -----------------------
// out[t,:] = dinv[t]^2 * h[t,:] (+b) + sum_{s in in(t)} dinv[t]*dinv[s]*h[s,:]
template<int D, bool ADDB>
__global__ void __launch_bounds__(256)
k_agg(const float* __restrict__ h, float* __restrict__ out,
      const float* __restrict__ bias) {
    int gw   = (blockIdx.x * 256 + threadIdx.x) >> 5;
    int lane = threadIdx.x & 31;
    if (gw >= NN) return;
    const float dt  = g_dinv[gw];
    const int   beg = g_rowptr[gw];
    const int   end = beg + ((int)g_deg[gw] - 1);
    const float4* hp = (const float4*)h;

    if (D == 128) {
        const int c4 = lane;                       // 32 chunks = full row
        float4 acc = hp[(size_t)gw * 32 + c4];
        float ws = dt * dt;
        acc.x *= ws; acc.y *= ws; acc.z *= ws; acc.w *= ws;
        int e = beg;
        for (; e + 2 <= end; e += 2) {
            int s0 = g_eidx[e], s1 = g_eidx[e + 1];
            float w0 = dt * g_dinv[s0], w1 = dt * g_dinv[s1];
            float4 v0 = hp[(size_t)s0 * 32 + c4];
            float4 v1 = hp[(size_t)s1 * 32 + c4];
            acc.x += w0 * v0.x + w1 * v1.x;
            acc.y += w0 * v0.y + w1 * v1.y;
            acc.z += w0 * v0.z + w1 * v1.z;
            acc.w += w0 * v0.w + w1 * v1.w;
        }
        if (e < end) {
            int s = g_eidx[e];
            float wv = dt * g_dinv[s];
            float4 v = hp[(size_t)s * 32 + c4];
            acc.x += wv * v.x; acc.y += wv * v.y;
            acc.z += wv * v.z; acc.w += wv * v.w;
        }
        ((float4*)out)[(size_t)gw * 32 + c4] = acc;
    } else {                                       // D = 64: two edges in flight
        const int c4   = lane & 15;                // 16 chunks = full row
        const int half = lane >> 4;
        float4 acc = make_float4(0.f, 0.f, 0.f, 0.f);
        if (half == 0) {
            acc = hp[(size_t)gw * 16 + c4];
            float ws = dt * dt;
            acc.x *= ws; acc.y *= ws; acc.z *= ws; acc.w *= ws;
            if (ADDB) {
                float4 b = ((const float4*)bias)[c4];
                acc.x += b.x; acc.y += b.y; acc.z += b.z; acc.w += b.w;
            }
        }
        for (int e = beg + half; e < end; e += 2) {
            int s = g_eidx[e];
            float wv = dt * g_dinv[s];
            float4 v = hp[(size_t)s * 16 + c4];
            acc.x += wv * v.x; acc.y += wv * v.y;
            acc.z += wv * v.z; acc.w += wv * v.w;
        }
        acc.x += __shfl_down_sync(0xffffffffu, acc.x, 16);
        acc.y += __shfl_down_sync(0xffffffffu, acc.y, 16);
        acc.z += __shfl_down_sync(0xffffffffu, acc.z, 16);
        acc.w += __shfl_down_sync(0xffffffffu, acc.w, 16);
        if (half == 0) ((float4*)out)[(size_t)gw * 16 + c4] = acc;
    }
}

// ---------------- launcher ----------------------------------------------------
extern "C" void kernel_launch(void* const* d_in, const int* in_sizes, int n_in,
                              void* d_out, int out_size) {
    const float* x  = (const float*)d_in[0];
    const int*   ei = (const int*)  d_in[1];
    const float* W1 = (const float*)d_in[2];
    const float* b1 = (const float*)d_in[3];
    const float* W2 = (const float*)d_in[4];
    const float* b2 = (const float*)d_in[5];
    float* out = (float*)d_out;

    const int* src = ei;
    const int* tgt = ei + NE;

    void *p_h1, *p_agg1, *p_h2;
    cudaGetSymbolAddress(&p_h1,   g_h1);
    cudaGetSymbolAddress(&p_agg1, g_agg1);
    cudaGetSymbolAddress(&p_h2,   g_h2);
    float* h1   = (float*)p_h1;
    float* agg1 = (float*)p_agg1;
    float* h2   = (float*)p_h2;

    const int smem1 = (256 * (KDIM + 4) + KDIM * (128 + 8)) * (int)sizeof(float); // 204800
    const int smem2 = (256 * (KDIM + 4) + KDIM * (64  + 8)) * (int)sizeof(float); // 172032
    cudaFuncSetAttribute((const void*)k_gemm_tc<128, 4, 4, 4, false>,
                         cudaFuncAttributeMaxDynamicSharedMemorySize, smem1);
    cudaFuncSetAttribute((const void*)k_gemm_tc<64, 8, 2, 4, true>,
                         cudaFuncAttributeMaxDynamicSharedMemorySize, smem2);

    // normalization + CSR build
    k_init_deg <<<(NN + 255) / 256, 256>>>();
    k_deg      <<<(NE + 255) / 256, 256>>>(tgt);
    k_dinv     <<<(NN + 255) / 256, 256>>>();
    k_scan_block<<<NB_SCAN, 256>>>();
    k_scan_spine<<<1, 128>>>();
    k_scan_add  <<<(NN + 255) / 256, 256>>>();
    k_fill      <<<(NE + 255) / 256, 256>>>(src, tgt);

    // layer 1: h1 = x @ W1 ; agg1 = self + CSR-aggregate
    k_gemm_tc<128, 4, 4, 4, false><<<(NN + 255) / 256, 512, smem1>>>(x, W1, nullptr, h1);
    k_agg<128, false><<<(NN * 32 + 255) / 256, 256>>>(h1, agg1, nullptr);

    // layer 2: h2 = relu(agg1+b1) @ W2 ; out = self + b2 + CSR-aggregate
    k_gemm_tc<64, 8, 2, 4, true><<<(NN + 255) / 256, 512, smem2>>>(agg1, W2, b1, h2);
    k_agg<64, true><<<(NN * 32 + 255) / 256, 256>>>(h2, out, b2);
}

// round 8
// speedup vs baseline: 3.5871x; 1.1798x over previous
#include <cuda_runtime.h>
#include <cuda_bf16.h>
#include <math.h>

// Problem constants (fixed by the reference)
#define NN 100000
#define NE 1600000
static constexpr int KDIM = 128;
static constexpr int HID  = 128;
static constexpr int OUTD = 64;
static constexpr int NB_SCAN = (NN + 1023) / 1024;

// ---------------- device scratch ---------------------------------------------
__device__ float g_deg [NN];
__device__ float g_dinv[NN];
__device__ int   g_rowptr[NN];
__device__ int   g_cursor[NN];
__device__ int   g_part[128];
__device__ int   g_eidx[NE];
__device__ float g_h1  [(size_t)NN * HID];
__device__ float g_agg1[(size_t)NN * HID];
__device__ float g_h2  [(size_t)NN * OUTD];

// ---------------- degree / normalization -------------------------------------
__global__ void k_init_deg() {
    int i = blockIdx.x * blockDim.x + threadIdx.x;
    if (i < NN) g_deg[i] = 1.0f;  // self-loop contributes 1
}
__global__ void k_deg(const int* __restrict__ tgt) {
    int e = blockIdx.x * blockDim.x + threadIdx.x;
    if (e < NE) atomicAdd(&g_deg[tgt[e]], 1.0f);
}

// ---------------- CSR build (scan fused with dinv) ----------------------------
__global__ void k_scan_block() {            // 256 thr, 4 items/thr
    __shared__ int sd[256];
    int tid  = threadIdx.x;
    int base = blockIdx.x * 1024 + tid * 4;
    int v[4], s = 0;
#pragma unroll
    for (int j = 0; j < 4; j++) {
        int i = base + j;
        int c = 0;
        if (i < NN) {
            float d = g_deg[i];
            g_dinv[i] = rsqrtf(d);          // fused dinv
            c = (int)d - 1;
        }
        v[j] = s; s += c;
    }
    sd[tid] = s; __syncthreads();
    for (int off = 1; off < 256; off <<= 1) {
        int t = (tid >= off) ? sd[tid - off] : 0;
        __syncthreads(); sd[tid] += t; __syncthreads();
    }
    int excl = sd[tid] - s;
#pragma unroll
    for (int j = 0; j < 4; j++) {
        int i = base + j;
        if (i < NN) g_rowptr[i] = excl + v[j];
    }
    if (tid == 255) g_part[blockIdx.x] = sd[255];
}

__global__ void k_scan_spine() {
    __shared__ int sp[128];
    int tid = threadIdx.x;
    int v = (tid < NB_SCAN) ? g_part[tid] : 0;
    sp[tid] = v; __syncthreads();
    for (int off = 1; off < 128; off <<= 1) {
        int t = (tid >= off) ? sp[tid - off] : 0;
        __syncthreads(); sp[tid] += t; __syncthreads();
    }
    g_part[tid] = sp[tid] - v;
}

__global__ void k_scan_add() {
    int i = blockIdx.x * blockDim.x + threadIdx.x;
    if (i < NN) {
        g_rowptr[i] += g_part[i >> 10];
        g_cursor[i] = 0;
    }
}

__global__ void k_fill(const int* __restrict__ src, const int* __restrict__ tgt) {
    int e = blockIdx.x * blockDim.x + threadIdx.x;
    if (e >= NE) return;
    int t = tgt[e];
    int pos = g_rowptr[t] + atomicAdd(&g_cursor[t], 1);
    g_eidx[pos] = src[e];
}

// ---------------- bf16 helpers -------------------------------------------------
// pack two floats into bf16x2: lo -> low half (smaller k), hi -> high half
__device__ __forceinline__ unsigned pk_bf16x2(float lo, float hi) {
    unsigned r;
    asm("cvt.rn.bf16x2.f32 %0, %1, %2;" : "=r"(r) : "f"(hi), "f"(lo));
    return r;
}
__device__ __forceinline__ float bf16_round(float x) {
    return __bfloat162float(__float2bfloat16_rn(x));
}

#define MMA_BF16(c, a, b)                                                     \
    asm volatile(                                                             \
        "mma.sync.aligned.m16n8k16.row.col.f32.bf16.bf16.f32 "                \
        "{%0,%1,%2,%3}, {%4,%5,%6,%7}, {%8,%9}, {%0,%1,%2,%3};"               \
        : "+f"((c)[0]), "+f"((c)[1]), "+f"((c)[2]), "+f"((c)[3])              \
        : "r"((a)[0]), "r"((a)[1]), "r"((a)[2]), "r"((a)[3]),                 \
          "r"((b)[0]), "r"((b)[1]))

// ---------------- 3x-bf16-split tensor-core GEMM ------------------------------
// CTA 512 thr, tile 256 x BN. A and W pre-split into bf16 hi/lo planes in smem
// at staging time -> inner loop is pure LDS + HMMA (no cvt ALU).
// Layouts: A[m][k] bf16 stride KS=136; W[n][k] bf16 stride KS (transposed).
// Frag 32-bit LDS hits banks (4*grp+q) mod 32 -> conflict-free.
// acc += ah*wh + ah*wl + al*wh  (lo*lo dropped, ~2^-16 rel)
// FUSE: A-tile gets relu(x + bin) on load.
template<int BN, int WMC, int MF, int NF, bool FUSE>
__global__ void __launch_bounds__(512)
k_gemm_bf(const float* __restrict__ A, const float* __restrict__ W,
          const float* __restrict__ bin, float* __restrict__ H) {
    constexpr int BM = 256;
    constexpr int KS = KDIM + 8;            // 136 bf16 elems (272B rows)
    constexpr int KW = KS / 2;              // 68 words per row

    extern __shared__ char smc[];
    unsigned* ah32 = (unsigned*)smc;                         // BM*KW words
    unsigned* al32 = ah32 + BM * KW;
    unsigned* wh32 = al32 + BM * KW;                         // BN*KW words
    unsigned* wl32 = wh32 + BN * KW;

    const int tid  = threadIdx.x;
    const int row0 = blockIdx.x * BM;

    // stage W transposed + split: thread handles 4 consecutive k at one n
    for (int i = tid; i < (KDIM / 4) * BN; i += 512) {
        int n  = i % BN;
        int kb = (i / BN) * 4;
        float f0 = W[(kb + 0) * BN + n];
        float f1 = W[(kb + 1) * BN + n];
        float f2 = W[(kb + 2) * BN + n];
        float f3 = W[(kb + 3) * BN + n];
        float h0 = bf16_round(f0), h1 = bf16_round(f1);
        float h2 = bf16_round(f2), h3 = bf16_round(f3);
        uint2 hw = make_uint2(pk_bf16x2(h0, h1), pk_bf16x2(h2, h3));
        uint2 lw = make_uint2(pk_bf16x2(f0 - h0, f1 - h1),
                              pk_bf16x2(f2 - h2, f3 - h3));
        int wi = (n * KW + kb / 2) >> 1;    // uint2 index
        ((uint2*)wh32)[wi] = hw;
        ((uint2*)wl32)[wi] = lw;
    }
    // stage A + split (row-major, coalesced float4 reads)
    for (int i = tid * 4; i < BM * KDIM; i += 512 * 4) {
        int r = i / KDIM, c = i % KDIM;
        int gr = row0 + r;
        float4 v = make_float4(0.f, 0.f, 0.f, 0.f);
        if (gr < NN) v = *(const float4*)(A + (size_t)gr * KDIM + c);
        if (FUSE) {
            float4 b = *(const float4*)(bin + c);
            v.x = fmaxf(v.x + b.x, 0.f);
            v.y = fmaxf(v.y + b.y, 0.f);
            v.z = fmaxf(v.z + b.z, 0.f);
            v.w = fmaxf(v.w + b.w, 0.f);
        }
        float h0 = bf16_round(v.x), h1 = bf16_round(v.y);
        float h2 = bf16_round(v.z), h3 = bf16_round(v.w);
        uint2 hw = make_uint2(pk_bf16x2(h0, h1), pk_bf16x2(h2, h3));
        uint2 lw = make_uint2(pk_bf16x2(v.x - h0, v.y - h1),
                              pk_bf16x2(v.z - h2, v.w - h3));
        int wi = (r * KW + c / 2) >> 1;
        ((uint2*)ah32)[wi] = hw;
        ((uint2*)al32)[wi] = lw;
    }
    __syncthreads();

    const int w    = tid >> 5, lane = tid & 31;
    const int wm   = w % WMC,  wn   = w / WMC;
    const int m0   = wm * (MF * 16), n0 = wn * (NF * 8);
    const int grp  = lane >> 2, q   = lane & 3;

    float acc[MF][NF][4];
#pragma unroll
    for (int i = 0; i < MF; i++)
#pragma unroll
        for (int j = 0; j < NF; j++)
#pragma unroll
            for (int t = 0; t < 4; t++) acc[i][j][t] = 0.f;

#pragma unroll 2
    for (int k0 = 0; k0 < KDIM; k0 += 16) {
        const int kw = (k0 >> 1) + q;
        unsigned ah[MF][4], al[MF][4];
#pragma unroll
        for (int mf = 0; mf < MF; mf++) {
            int m = m0 + mf * 16 + grp;
            ah[mf][0] = ah32[m * KW + kw];
            ah[mf][1] = ah32[(m + 8) * KW + kw];
            ah[mf][2] = ah32[m * KW + kw + 4];
            ah[mf][3] = ah32[(m + 8) * KW + kw + 4];
            al[mf][0] = al32[m * KW + kw];
            al[mf][1] = al32[(m + 8) * KW + kw];
            al[mf][2] = al32[m * KW + kw + 4];
            al[mf][3] = al32[(m + 8) * KW + kw + 4];
        }
        unsigned bh[NF][2], bl[NF][2];
#pragma unroll
        for (int nf = 0; nf < NF; nf++) {
            int n = n0 + nf * 8 + grp;
            bh[nf][0] = wh32[n * KW + kw];
            bh[nf][1] = wh32[n * KW + kw + 4];
            bl[nf][0] = wl32[n * KW + kw];
            bl[nf][1] = wl32[n * KW + kw + 4];
        }
#pragma unroll
        for (int mf = 0; mf < MF; mf++)
#pragma unroll
            for (int nf = 0; nf < NF; nf++) {
                MMA_BF16(acc[mf][nf], ah[mf], bh[nf]);
                MMA_BF16(acc[mf][nf], ah[mf], bl[nf]);
                MMA_BF16(acc[mf][nf], al[mf], bh[nf]);
            }
    }

#pragma unroll
    for (int mf = 0; mf < MF; mf++) {
        int r1 = row0 + m0 + mf * 16 + grp;
        int r2 = r1 + 8;
#pragma unroll
        for (int nf = 0; nf < NF; nf++) {
            int col = n0 + nf * 8 + 2 * q;
            if (r1 < NN)
                *(float2*)(H + (size_t)r1 * BN + col) =
                    make_float2(acc[mf][nf][0], acc[mf][nf][1]);
            if (r2 < NN)
                *(float2*)(H + (size_t)r2 * BN + col) =
                    make_float2(acc[mf][nf][2], acc[mf][nf][3]);
        }
    }
}

// ---------------- CSR aggregation: warp per target node -----------------------
template<int D, bool ADDB>
__global__ void __launch_bounds__(256)
k_agg(const float* __restrict__ h, float* __restrict__ out,
      const float* __restrict__ bias) {
    int gw   = (blockIdx.x * 256 + threadIdx.x) >> 5;
    int lane = threadIdx.x & 31;
    if (gw >= NN) return;
    const float dt  = g_dinv[gw];
    const int   beg = g_rowptr[gw];
    const int   end = beg + ((int)g_deg[gw] - 1);
    const float4* hp = (const float4*)h;

    if (D == 128) {
        const int c4 = lane;
        float4 acc = hp[(size_t)gw * 32 + c4];
        float ws = dt * dt;
        acc.x *= ws; acc.y *= ws; acc.z *= ws; acc.w *= ws;
        int e = beg;
        for (; e + 2 <= end; e += 2) {
            int s0 = g_eidx[e], s1 = g_eidx[e + 1];
            float w0 = dt * g_dinv[s0], w1 = dt * g_dinv[s1];
            float4 v0 = hp[(size_t)s0 * 32 + c4];
            float4 v1 = hp[(size_t)s1 * 32 + c4];
            acc.x += w0 * v0.x + w1 * v1.x;
            acc.y += w0 * v0.y + w1 * v1.y;
            acc.z += w0 * v0.z + w1 * v1.z;
            acc.w += w0 * v0.w + w1 * v1.w;
        }
        if (e < end) {
            int s = g_eidx[e];
            float wv = dt * g_dinv[s];
            float4 v = hp[(size_t)s * 32 + c4];
            acc.x += wv * v.x; acc.y += wv * v.y;
            acc.z += wv * v.z; acc.w += wv * v.w;
        }
        ((float4*)out)[(size_t)gw * 32 + c4] = acc;
    } else {
        const int c4   = lane & 15;
        const int half = lane >> 4;
        float4 acc = make_float4(0.f, 0.f, 0.f, 0.f);
        if (half == 0) {
            acc = hp[(size_t)gw * 16 + c4];
            float ws = dt * dt;
            acc.x *= ws; acc.y *= ws; acc.z *= ws; acc.w *= ws;
            if (ADDB) {
                float4 b = ((const float4*)bias)[c4];
                acc.x += b.x; acc.y += b.y; acc.z += b.z; acc.w += b.w;
            }
        }
        for (int e = beg + half; e < end; e += 2) {
            int s = g_eidx[e];
            float wv = dt * g_dinv[s];
            float4 v = hp[(size_t)s * 16 + c4];
            acc.x += wv * v.x; acc.y += wv * v.y;
            acc.z += wv * v.z; acc.w += wv * v.w;
        }
        acc.x += __shfl_down_sync(0xffffffffu, acc.x, 16);
        acc.y += __shfl_down_sync(0xffffffffu, acc.y, 16);
        acc.z += __shfl_down_sync(0xffffffffu, acc.z, 16);
        acc.w += __shfl_down_sync(0xffffffffu, acc.w, 16);
        if (half == 0) ((float4*)out)[(size_t)gw * 16 + c4] = acc;
    }
}

// ---------------- launcher ----------------------------------------------------
extern "C" void kernel_launch(void* const* d_in, const int* in_sizes, int n_in,
                              void* d_out, int out_size) {
    const float* x  = (const float*)d_in[0];
    const int*   ei = (const int*)  d_in[1];
    const float* W1 = (const float*)d_in[2];
    const float* b1 = (const float*)d_in[3];
    const float* W2 = (const float*)d_in[4];
    const float* b2 = (const float*)d_in[5];
    float* out = (float*)d_out;

    const int* src = ei;
    const int* tgt = ei + NE;

    void *p_h1, *p_agg1, *p_h2;
    cudaGetSymbolAddress(&p_h1,   g_h1);
    cudaGetSymbolAddress(&p_agg1, g_agg1);
    cudaGetSymbolAddress(&p_h2,   g_h2);
    float* h1   = (float*)p_h1;
    float* agg1 = (float*)p_agg1;
    float* h2   = (float*)p_h2;

    constexpr int KW = (KDIM + 8) / 2;                       // 68 words
    const int smem1 = (2 * 256 * KW + 2 * 128 * KW) * 4;     // 208896 B
    const int smem2 = (2 * 256 * KW + 2 * 64  * KW) * 4;     // 174080 B
    cudaFuncSetAttribute((const void*)k_gemm_bf<128, 4, 4, 4, false>,
                         cudaFuncAttributeMaxDynamicSharedMemorySize, smem1);
    cudaFuncSetAttribute((const void*)k_gemm_bf<64, 8, 2, 4, true>,
                         cudaFuncAttributeMaxDynamicSharedMemorySize, smem2);

    // normalization + CSR build
    k_init_deg  <<<(NN + 255) / 256, 256>>>();
    k_deg       <<<(NE + 255) / 256, 256>>>(tgt);
    k_scan_block<<<NB_SCAN, 256>>>();
    k_scan_spine<<<1, 128>>>();
    k_scan_add  <<<(NN + 255) / 256, 256>>>();
    k_fill      <<<(NE + 255) / 256, 256>>>(src, tgt);

    // layer 1
    k_gemm_bf<128, 4, 4, 4, false><<<(NN + 255) / 256, 512, smem1>>>(x, W1, nullptr, h1);
    k_agg<128, false><<<(NN * 32 + 255) / 256, 256>>>(h1, agg1, nullptr);

    // layer 2
    k_gemm_bf<64, 8, 2, 4, true><<<(NN + 255) / 256, 512, smem2>>>(agg1, W2, b1, h2);
    k_agg<64, true><<<(NN * 32 + 255) / 256, 256>>>(h2, out, b2);
}

// round 9
// speedup vs baseline: 3.9865x; 1.1113x over previous
#include <cuda_runtime.h>
#include <cuda_bf16.h>
#include <cuda_fp16.h>
#include <math.h>

// Problem constants (fixed by the reference)
#define NN 100000
#define NE 1600000
static constexpr int KDIM = 128;
static constexpr int HID  = 128;
static constexpr int OUTD = 64;
static constexpr int NB_SCAN = (NN + 1023) / 1024;

// ---------------- device scratch ---------------------------------------------
__device__ float  g_deg [NN];
__device__ float  g_dinv[NN];
__device__ int    g_rowptr[NN];
__device__ int    g_cursor[NN];
__device__ int    g_part[128];
__device__ int    g_eidx[NE];
__device__ __half g_h1  [(size_t)NN * HID];    // fp16 features for gather
__device__ float  g_agg1[(size_t)NN * HID];    // fp32 aggregate (GEMM2 input)
__device__ __half g_h2  [(size_t)NN * OUTD];

// ---------------- degree / normalization -------------------------------------
__global__ void k_init_deg() {
    int i = blockIdx.x * blockDim.x + threadIdx.x;
    if (i < NN) g_deg[i] = 1.0f;  // self-loop contributes 1
}
__global__ void k_deg(const int* __restrict__ tgt) {
    int e = blockIdx.x * blockDim.x + threadIdx.x;
    if (e < NE) atomicAdd(&g_deg[tgt[e]], 1.0f);
}

// ---------------- CSR build (scan fused with dinv) ----------------------------
__global__ void k_scan_block() {            // 256 thr, 4 items/thr
    __shared__ int sd[256];
    int tid  = threadIdx.x;
    int base = blockIdx.x * 1024 + tid * 4;
    int v[4], s = 0;
#pragma unroll
    for (int j = 0; j < 4; j++) {
        int i = base + j;
        int c = 0;
        if (i < NN) {
            float d = g_deg[i];
            g_dinv[i] = rsqrtf(d);          // fused dinv
            c = (int)d - 1;
        }
        v[j] = s; s += c;
    }
    sd[tid] = s; __syncthreads();
    for (int off = 1; off < 256; off <<= 1) {
        int t = (tid >= off) ? sd[tid - off] : 0;
        __syncthreads(); sd[tid] += t; __syncthreads();
    }
    int excl = sd[tid] - s;
#pragma unroll
    for (int j = 0; j < 4; j++) {
        int i = base + j;
        if (i < NN) g_rowptr[i] = excl + v[j];
    }
    if (tid == 255) g_part[blockIdx.x] = sd[255];
}

__global__ void k_scan_spine() {
    __shared__ int sp[128];
    int tid = threadIdx.x;
    int v = (tid < NB_SCAN) ? g_part[tid] : 0;
    sp[tid] = v; __syncthreads();
    for (int off = 1; off < 128; off <<= 1) {
        int t = (tid >= off) ? sp[tid - off] : 0;
        __syncthreads(); sp[tid] += t; __syncthreads();
    }
    g_part[tid] = sp[tid] - v;
}

__global__ void k_scan_add() {
    int i = blockIdx.x * blockDim.x + threadIdx.x;
    if (i < NN) {
        g_rowptr[i] += g_part[i >> 10];
        g_cursor[i] = 0;
    }
}

__global__ void k_fill(const int* __restrict__ src, const int* __restrict__ tgt) {
    int e = blockIdx.x * blockDim.x + threadIdx.x;
    if (e >= NE) return;
    int t = tgt[e];
    int pos = g_rowptr[t] + atomicAdd(&g_cursor[t], 1);
    g_eidx[pos] = src[e];
}

// ---------------- bf16 helpers -------------------------------------------------
__device__ __forceinline__ unsigned pk_bf16x2(float lo, float hi) {
    unsigned r;
    asm("cvt.rn.bf16x2.f32 %0, %1, %2;" : "=r"(r) : "f"(hi), "f"(lo));
    return r;
}
__device__ __forceinline__ float bf16_round(float x) {
    return __bfloat162float(__float2bfloat16_rn(x));
}

#define MMA_BF16(c, a, b)                                                     \
    asm volatile(                                                             \
        "mma.sync.aligned.m16n8k16.row.col.f32.bf16.bf16.f32 "                \
        "{%0,%1,%2,%3}, {%4,%5,%6,%7}, {%8,%9}, {%0,%1,%2,%3};"               \
        : "+f"((c)[0]), "+f"((c)[1]), "+f"((c)[2]), "+f"((c)[3])              \
        : "r"((a)[0]), "r"((a)[1]), "r"((a)[2]), "r"((a)[3]),                 \
          "r"((b)[0]), "r"((b)[1]))

// ---------------- 3x-bf16-split tensor-core GEMM (fp16 output) ----------------
// CTA 512 thr, tile 256 x BN. A and W pre-split into bf16 hi/lo planes in smem.
// Inner loop is pure LDS + HMMA. Epilogue emits fp16 (gather consumer).
template<int BN, int WMC, int MF, int NF, bool FUSE>
__global__ void __launch_bounds__(512)
k_gemm_bf(const float* __restrict__ A, const float* __restrict__ W,
          const float* __restrict__ bin, __half* __restrict__ H) {
    constexpr int BM = 256;
    constexpr int KS = KDIM + 8;            // 136 bf16 elems
    constexpr int KW = KS / 2;              // 68 words per row

    extern __shared__ char smc[];
    unsigned* ah32 = (unsigned*)smc;
    unsigned* al32 = ah32 + BM * KW;
    unsigned* wh32 = al32 + BM * KW;
    unsigned* wl32 = wh32 + BN * KW;

    const int tid  = threadIdx.x;
    const int row0 = blockIdx.x * BM;

    // stage W transposed + split
    for (int i = tid; i < (KDIM / 4) * BN; i += 512) {
        int n  = i % BN;
        int kb = (i / BN) * 4;
        float f0 = W[(kb + 0) * BN + n];
        float f1 = W[(kb + 1) * BN + n];
        float f2 = W[(kb + 2) * BN + n];
        float f3 = W[(kb + 3) * BN + n];
        float h0 = bf16_round(f0), h1 = bf16_round(f1);
        float h2 = bf16_round(f2), h3 = bf16_round(f3);
        uint2 hw = make_uint2(pk_bf16x2(h0, h1), pk_bf16x2(h2, h3));
        uint2 lw = make_uint2(pk_bf16x2(f0 - h0, f1 - h1),
                              pk_bf16x2(f2 - h2, f3 - h3));
        int wi = (n * KW + kb / 2) >> 1;
        ((uint2*)wh32)[wi] = hw;
        ((uint2*)wl32)[wi] = lw;
    }
    // stage A + split
    for (int i = tid * 4; i < BM * KDIM; i += 512 * 4) {
        int r = i / KDIM, c = i % KDIM;
        int gr = row0 + r;
        float4 v = make_float4(0.f, 0.f, 0.f, 0.f);
        if (gr < NN) v = *(const float4*)(A + (size_t)gr * KDIM + c);
        if (FUSE) {
            float4 b = *(const float4*)(bin + c);
            v.x = fmaxf(v.x + b.x, 0.f);
            v.y = fmaxf(v.y + b.y, 0.f);
            v.z = fmaxf(v.z + b.z, 0.f);
            v.w = fmaxf(v.w + b.w, 0.f);
        }
        float h0 = bf16_round(v.x), h1 = bf16_round(v.y);
        float h2 = bf16_round(v.z), h3 = bf16_round(v.w);
        uint2 hw = make_uint2(pk_bf16x2(h0, h1), pk_bf16x2(h2, h3));
        uint2 lw = make_uint2(pk_bf16x2(v.x - h0, v.y - h1),
                              pk_bf16x2(v.z - h2, v.w - h3));
        int wi = (r * KW + c / 2) >> 1;
        ((uint2*)ah32)[wi] = hw;
        ((uint2*)al32)[wi] = lw;
    }
    __syncthreads();

    const int w    = tid >> 5, lane = tid & 31;
    const int wm   = w % WMC,  wn   = w / WMC;
    const int m0   = wm * (MF * 16), n0 = wn * (NF * 8);
    const int grp  = lane >> 2, q   = lane & 3;

    float acc[MF][NF][4];
#pragma unroll
    for (int i = 0; i < MF; i++)
#pragma unroll
        for (int j = 0; j < NF; j++)
#pragma unroll
            for (int t = 0; t < 4; t++) acc[i][j][t] = 0.f;

#pragma unroll 2
    for (int k0 = 0; k0 < KDIM; k0 += 16) {
        const int kw = (k0 >> 1) + q;
        unsigned ah[MF][4], al[MF][4];
#pragma unroll
        for (int mf = 0; mf < MF; mf++) {
            int m = m0 + mf * 16 + grp;
            ah[mf][0] = ah32[m * KW + kw];
            ah[mf][1] = ah32[(m + 8) * KW + kw];
            ah[mf][2] = ah32[m * KW + kw + 4];
            ah[mf][3] = ah32[(m + 8) * KW + kw + 4];
            al[mf][0] = al32[m * KW + kw];
            al[mf][1] = al32[(m + 8) * KW + kw];
            al[mf][2] = al32[m * KW + kw + 4];
            al[mf][3] = al32[(m + 8) * KW + kw + 4];
        }
        unsigned bh[NF][2], bl[NF][2];
#pragma unroll
        for (int nf = 0; nf < NF; nf++) {
            int n = n0 + nf * 8 + grp;
            bh[nf][0] = wh32[n * KW + kw];
            bh[nf][1] = wh32[n * KW + kw + 4];
            bl[nf][0] = wl32[n * KW + kw];
            bl[nf][1] = wl32[n * KW + kw + 4];
        }
#pragma unroll
        for (int mf = 0; mf < MF; mf++)
#pragma unroll
            for (int nf = 0; nf < NF; nf++) {
                MMA_BF16(acc[mf][nf], ah[mf], bh[nf]);
                MMA_BF16(acc[mf][nf], ah[mf], bl[nf]);
                MMA_BF16(acc[mf][nf], al[mf], bh[nf]);
            }
    }

#pragma unroll
    for (int mf = 0; mf < MF; mf++) {
        int r1 = row0 + m0 + mf * 16 + grp;
        int r2 = r1 + 8;
#pragma unroll
        for (int nf = 0; nf < NF; nf++) {
            int col = n0 + nf * 8 + 2 * q;
            if (r1 < NN)
                *(__half2*)(H + (size_t)r1 * BN + col) =
                    __floats2half2_rn(acc[mf][nf][0], acc[mf][nf][1]);
            if (r2 < NN)
                *(__half2*)(H + (size_t)r2 * BN + col) =
                    __floats2half2_rn(acc[mf][nf][2], acc[mf][nf][3]);
        }
    }
}

// ---------------- CSR aggregation: warp per target node, fp16 gather ----------
__device__ __forceinline__ float4 up4(uint2 r) {
    float2 fa = __half22float2(*(__half2*)&r.x);
    float2 fb = __half22float2(*(__half2*)&r.y);
    return make_float4(fa.x, fa.y, fb.x, fb.y);
}

// out[t,:] = dinv[t]^2 * h[t,:] (+b) + sum_{s in in(t)} dinv[t]*dinv[s]*h[s,:]
template<int D, bool ADDB>
__global__ void __launch_bounds__(256)
k_agg(const __half* __restrict__ h, float* __restrict__ out,
      const float* __restrict__ bias) {
    int gw   = (blockIdx.x * 256 + threadIdx.x) >> 5;
    int lane = threadIdx.x & 31;
    if (gw >= NN) return;
    const float dt  = g_dinv[gw];
    const int   beg = g_rowptr[gw];
    const int   end = beg + ((int)g_deg[gw] - 1);
    const uint2* hp = (const uint2*)h;           // 4 halfs per uint2

    if (D == 128) {
        const int c = lane;                      // 32 uint2 chunks = full row
        float4 acc = up4(hp[(size_t)gw * 32 + c]);
        float ws = dt * dt;
        acc.x *= ws; acc.y *= ws; acc.z *= ws; acc.w *= ws;
        int e = beg;
        for (; e + 2 <= end; e += 2) {
            int s0 = g_eidx[e], s1 = g_eidx[e + 1];
            float w0 = dt * g_dinv[s0], w1 = dt * g_dinv[s1];
            float4 v0 = up4(hp[(size_t)s0 * 32 + c]);
            float4 v1 = up4(hp[(size_t)s1 * 32 + c]);
            acc.x += w0 * v0.x + w1 * v1.x;
            acc.y += w0 * v0.y + w1 * v1.y;
            acc.z += w0 * v0.z + w1 * v1.z;
            acc.w += w0 * v0.w + w1 * v1.w;
        }
        if (e < end) {
            int s = g_eidx[e];
            float wv = dt * g_dinv[s];
            float4 v = up4(hp[(size_t)s * 32 + c]);
            acc.x += wv * v.x; acc.y += wv * v.y;
            acc.z += wv * v.z; acc.w += wv * v.w;
        }
        ((float4*)out)[(size_t)gw * 32 + c] = acc;
    } else {                                     // D=64: 16 chunks, 2 edges in flight
        const int c    = lane & 15;
        const int half = lane >> 4;
        float4 acc = make_float4(0.f, 0.f, 0.f, 0.f);
        if (half == 0) {
            acc = up4(hp[(size_t)gw * 16 + c]);
            float ws = dt * dt;
            acc.x *= ws; acc.y *= ws; acc.z *= ws; acc.w *= ws;
            if (ADDB) {
                float4 b = ((const float4*)bias)[c];
                acc.x += b.x; acc.y += b.y; acc.z += b.z; acc.w += b.w;
            }
        }
        for (int e = beg + half; e < end; e += 2) {
            int s = g_eidx[e];
            float wv = dt * g_dinv[s];
            float4 v = up4(hp[(size_t)s * 16 + c]);
            acc.x += wv * v.x; acc.y += wv * v.y;
            acc.z += wv * v.z; acc.w += wv * v.w;
        }
        acc.x += __shfl_down_sync(0xffffffffu, acc.x, 16);
        acc.y += __shfl_down_sync(0xffffffffu, acc.y, 16);
        acc.z += __shfl_down_sync(0xffffffffu, acc.z, 16);
        acc.w += __shfl_down_sync(0xffffffffu, acc.w, 16);
        if (half == 0) ((float4*)out)[(size_t)gw * 16 + c] = acc;
    }
}

// ---------------- launcher ----------------------------------------------------
extern "C" void kernel_launch(void* const* d_in, const int* in_sizes, int n_in,
                              void* d_out, int out_size) {
    const float* x  = (const float*)d_in[0];
    const int*   ei = (const int*)  d_in[1];
    const float* W1 = (const float*)d_in[2];
    const float* b1 = (const float*)d_in[3];
    const float* W2 = (const float*)d_in[4];
    const float* b2 = (const float*)d_in[5];
    float* out = (float*)d_out;

    const int* src = ei;
    const int* tgt = ei + NE;

    void *p_h1, *p_agg1, *p_h2;
    cudaGetSymbolAddress(&p_h1,   g_h1);
    cudaGetSymbolAddress(&p_agg1, g_agg1);
    cudaGetSymbolAddress(&p_h2,   g_h2);
    __half* h1   = (__half*)p_h1;
    float*  agg1 = (float*) p_agg1;
    __half* h2   = (__half*)p_h2;

    constexpr int KW = (KDIM + 8) / 2;
    const int smem1 = (2 * 256 * KW + 2 * 128 * KW) * 4;     // 208896 B
    const int smem2 = (2 * 256 * KW + 2 * 64  * KW) * 4;     // 174080 B
    cudaFuncSetAttribute((const void*)k_gemm_bf<128, 4, 4, 4, false>,
                         cudaFuncAttributeMaxDynamicSharedMemorySize, smem1);
    cudaFuncSetAttribute((const void*)k_gemm_bf<64, 8, 2, 4, true>,
                         cudaFuncAttributeMaxDynamicSharedMemorySize, smem2);

    // side stream + fork/join events (created once; work is identical per call)
    static cudaStream_t s_csr = nullptr;
    static cudaEvent_t  ev_fork = nullptr, ev_join = nullptr;
    if (!s_csr) {
        cudaStreamCreateWithFlags(&s_csr, cudaStreamNonBlocking);
        cudaEventCreateWithFlags(&ev_fork, cudaEventDisableTiming);
        cudaEventCreateWithFlags(&ev_join, cudaEventDisableTiming);
    }

    // fork: CSR build runs concurrently with GEMM1
    cudaEventRecord(ev_fork, 0);
    cudaStreamWaitEvent(s_csr, ev_fork, 0);
    k_init_deg  <<<(NN + 255) / 256, 256, 0, s_csr>>>();
    k_deg       <<<(NE + 255) / 256, 256, 0, s_csr>>>(tgt);
    k_scan_block<<<NB_SCAN, 256, 0, s_csr>>>();
    k_scan_spine<<<1, 128, 0, s_csr>>>();
    k_scan_add  <<<(NN + 255) / 256, 256, 0, s_csr>>>();
    k_fill      <<<(NE + 255) / 256, 256, 0, s_csr>>>(src, tgt);
    cudaEventRecord(ev_join, s_csr);

    // GEMM1 on main stream (independent of CSR)
    k_gemm_bf<128, 4, 4, 4, false><<<(NN + 255) / 256, 512, smem1>>>(x, W1, nullptr, h1);

    // join, then aggregate / layer 2
    cudaStreamWaitEvent(0, ev_join, 0);
    k_agg<128, false><<<(NN * 32 + 255) / 256, 256>>>(h1, agg1, nullptr);
    k_gemm_bf<64, 8, 2, 4, true><<<(NN + 255) / 256, 512, smem2>>>(agg1, W2, b1, h2);
    k_agg<64, true><<<(NN * 32 + 255) / 256, 256>>>(h2, out, b2);
}

// round 12
// speedup vs baseline: 4.0984x; 1.0281x over previous
#include <cuda_runtime.h>
#include <cuda_bf16.h>
#include <cuda_fp16.h>
#include <stdint.h>
#include <math.h>

// Problem constants (fixed by the reference)
#define NN 100000
#define NE 1600000
static constexpr int KDIM = 128;
static constexpr int HID  = 128;
static constexpr int OUTD = 64;
static constexpr int NB_SCAN = (NN + 1023) / 1024;

// ---------------- device scratch ---------------------------------------------
__device__ float  g_deg [NN];
__device__ float  g_dinv[NN];
__device__ int    g_rowptr[NN];
__device__ int    g_cursor[NN];
__device__ int    g_part[128];
__device__ int    g_eidx[NE];
__device__ __half g_h1  [(size_t)NN * HID];    // fp16 features (layer-1 GEMM out)
__device__ __half g_a1h [(size_t)NN * HID];    // fp16 relu(agg1+b1) (GEMM2 input)
__device__ __half g_h2  [(size_t)NN * OUTD];

// ---------------- degree / normalization -------------------------------------
__global__ void k_init_deg() {
    int i = blockIdx.x * blockDim.x + threadIdx.x;
    if (i < NN) g_deg[i] = 1.0f;
}
__global__ void k_deg(const int* __restrict__ tgt) {
    int e = blockIdx.x * blockDim.x + threadIdx.x;
    if (e < NE) atomicAdd(&g_deg[tgt[e]], 1.0f);
}

// ---------------- CSR build (scan fused with dinv) ----------------------------
__global__ void k_scan_block() {
    __shared__ int sd[256];
    int tid  = threadIdx.x;
    int base = blockIdx.x * 1024 + tid * 4;
    int v[4], s = 0;
#pragma unroll
    for (int j = 0; j < 4; j++) {
        int i = base + j;
        int c = 0;
        if (i < NN) {
            float d = g_deg[i];
            g_dinv[i] = rsqrtf(d);
            c = (int)d - 1;
        }
        v[j] = s; s += c;
    }
    sd[tid] = s; __syncthreads();
    for (int off = 1; off < 256; off <<= 1) {
        int t = (tid >= off) ? sd[tid - off] : 0;
        __syncthreads(); sd[tid] += t; __syncthreads();
    }
    int excl = sd[tid] - s;
#pragma unroll
    for (int j = 0; j < 4; j++) {
        int i = base + j;
        if (i < NN) g_rowptr[i] = excl + v[j];
    }
    if (tid == 255) g_part[blockIdx.x] = sd[255];
}

__global__ void k_scan_spine() {
    __shared__ int sp[128];
    int tid = threadIdx.x;
    int v = (tid < NB_SCAN) ? g_part[tid] : 0;
    sp[tid] = v; __syncthreads();
    for (int off = 1; off < 128; off <<= 1) {
        int t = (tid >= off) ? sp[tid - off] : 0;
        __syncthreads(); sp[tid] += t; __syncthreads();
    }
    g_part[tid] = sp[tid] - v;
}

__global__ void k_scan_add() {
    int i = blockIdx.x * blockDim.x + threadIdx.x;
    if (i < NN) {
        g_rowptr[i] += g_part[i >> 10];
        g_cursor[i] = 0;
    }
}

__global__ void k_fill(const int* __restrict__ src, const int* __restrict__ tgt) {
    int e = blockIdx.x * blockDim.x + threadIdx.x;
    if (e >= NE) return;
    int t = tgt[e];
    int pos = g_rowptr[t] + atomicAdd(&g_cursor[t], 1);
    g_eidx[pos] = src[e];
}

// ---------------- bf16 / fp16 helpers -----------------------------------------
__device__ __forceinline__ unsigned pk_bf16x2(float lo, float hi) {
    unsigned r;
    asm("cvt.rn.bf16x2.f32 %0, %1, %2;" : "=r"(r) : "f"(hi), "f"(lo));
    return r;
}
__device__ __forceinline__ float bf16_round(float x) {
    return __bfloat162float(__float2bfloat16_rn(x));
}
__device__ __forceinline__ float4 up4(uint2 r) {
    float2 fa = __half22float2(*(__half2*)&r.x);
    float2 fb = __half22float2(*(__half2*)&r.y);
    return make_float4(fa.x, fa.y, fb.x, fb.y);
}

#define MMA_BF16(c, a, b)                                                     \
    asm volatile(                                                             \
        "mma.sync.aligned.m16n8k16.row.col.f32.bf16.bf16.f32 "                \
        "{%0,%1,%2,%3}, {%4,%5,%6,%7}, {%8,%9}, {%0,%1,%2,%3};"               \
        : "+f"((c)[0]), "+f"((c)[1]), "+f"((c)[2]), "+f"((c)[3])              \
        : "r"((a)[0]), "r"((a)[1]), "r"((a)[2]), "r"((a)[3]),                 \
          "r"((b)[0]), "r"((b)[1]))

// ---------------- 3x-bf16-split tensor-core GEMM (fp16 output) ----------------
// CTA 512 thr, tile 256 x BN. A and W pre-split into bf16 hi/lo planes in smem.
// AT = float (layer 1 input) or __half (layer 2 input, already relu+bias'd).
template<int BN, int WMC, int MF, int NF, typename AT>
__global__ void __launch_bounds__(512)
k_gemm_bf(const AT* __restrict__ A, const float* __restrict__ W,
          __half* __restrict__ H) {
    constexpr int BM = 256;
    constexpr int KS = KDIM + 8;            // 136 bf16 elems
    constexpr int KW = KS / 2;              // 68 words per row

    extern __shared__ char smc[];
    unsigned* ah32 = (unsigned*)smc;
    unsigned* al32 = ah32 + BM * KW;
    unsigned* wh32 = al32 + BM * KW;
    unsigned* wl32 = wh32 + BN * KW;

    const int tid  = threadIdx.x;
    const int row0 = blockIdx.x * BM;

    // stage W transposed + split
    for (int i = tid; i < (KDIM / 4) * BN; i += 512) {
        int n  = i % BN;
        int kb = (i / BN) * 4;
        float f0 = W[(kb + 0) * BN + n];
        float f1 = W[(kb + 1) * BN + n];
        float f2 = W[(kb + 2) * BN + n];
        float f3 = W[(kb + 3) * BN + n];
        float h0 = bf16_round(f0), h1 = bf16_round(f1);
        float h2 = bf16_round(f2), h3 = bf16_round(f3);
        uint2 hw = make_uint2(pk_bf16x2(h0, h1), pk_bf16x2(h2, h3));
        uint2 lw = make_uint2(pk_bf16x2(f0 - h0, f1 - h1),
                              pk_bf16x2(f2 - h2, f3 - h3));
        int wi = (n * KW + kb / 2) >> 1;
        ((uint2*)wh32)[wi] = hw;
        ((uint2*)wl32)[wi] = lw;
    }
    // stage A + split
    for (int i = tid * 4; i < BM * KDIM; i += 512 * 4) {
        int r = i / KDIM, c = i % KDIM;
        int gr = row0 + r;
        float4 v = make_float4(0.f, 0.f, 0.f, 0.f);
        if (gr < NN) {
            if (sizeof(AT) == 4) {
                v = *(const float4*)((const float*)A + (size_t)gr * KDIM + c);
            } else {
                v = up4(*(const uint2*)((const __half*)A + (size_t)gr * KDIM + c));
            }
        }
        float h0 = bf16_round(v.x), h1 = bf16_round(v.y);
        float h2 = bf16_round(v.z), h3 = bf16_round(v.w);
        uint2 hw = make_uint2(pk_bf16x2(h0, h1), pk_bf16x2(h2, h3));
        uint2 lw = make_uint2(pk_bf16x2(v.x - h0, v.y - h1),
                              pk_bf16x2(v.z - h2, v.w - h3));
        int wi = (r * KW + c / 2) >> 1;
        ((uint2*)ah32)[wi] = hw;
        ((uint2*)al32)[wi] = lw;
    }
    __syncthreads();

    const int w    = tid >> 5, lane = tid & 31;
    const int wm   = w % WMC,  wn   = w / WMC;
    const int m0   = wm * (MF * 16), n0 = wn * (NF * 8);
    const int grp  = lane >> 2, q   = lane & 3;

    float acc[MF][NF][4];
#pragma unroll
    for (int i = 0; i < MF; i++)
#pragma unroll
        for (int j = 0; j < NF; j++)
#pragma unroll
            for (int t = 0; t < 4; t++) acc[i][j][t] = 0.f;

#pragma unroll 2
    for (int k0 = 0; k0 < KDIM; k0 += 16) {
        const int kw = (k0 >> 1) + q;
        unsigned ah[MF][4], al[MF][4];
#pragma unroll
        for (int mf = 0; mf < MF; mf++) {
            int m = m0 + mf * 16 + grp;
            ah[mf][0] = ah32[m * KW + kw];
            ah[mf][1] = ah32[(m + 8) * KW + kw];
            ah[mf][2] = ah32[m * KW + kw + 4];
            ah[mf][3] = ah32[(m + 8) * KW + kw + 4];
            al[mf][0] = al32[m * KW + kw];
            al[mf][1] = al32[(m + 8) * KW + kw];
            al[mf][2] = al32[m * KW + kw + 4];
            al[mf][3] = al32[(m + 8) * KW + kw + 4];
        }
        unsigned bh[NF][2], bl[NF][2];
#pragma unroll
        for (int nf = 0; nf < NF; nf++) {
            int n = n0 + nf * 8 + grp;
            bh[nf][0] = wh32[n * KW + kw];
            bh[nf][1] = wh32[n * KW + kw + 4];
            bl[nf][0] = wl32[n * KW + kw];
            bl[nf][1] = wl32[n * KW + kw + 4];
        }
#pragma unroll
        for (int mf = 0; mf < MF; mf++)
#pragma unroll
            for (int nf = 0; nf < NF; nf++) {
                MMA_BF16(acc[mf][nf], ah[mf], bh[nf]);
                MMA_BF16(acc[mf][nf], ah[mf], bl[nf]);
                MMA_BF16(acc[mf][nf], al[mf], bh[nf]);
            }
    }

#pragma unroll
    for (int mf = 0; mf < MF; mf++) {
        int r1 = row0 + m0 + mf * 16 + grp;
        int r2 = r1 + 8;
#pragma unroll
        for (int nf = 0; nf < NF; nf++) {
            int col = n0 + nf * 8 + 2 * q;
            if (r1 < NN)
                *(__half2*)(H + (size_t)r1 * BN + col) =
                    __floats2half2_rn(acc[mf][nf][0], acc[mf][nf][1]);
            if (r2 < NN)
                *(__half2*)(H + (size_t)r2 * BN + col) =
                    __floats2half2_rn(acc[mf][nf][2], acc[mf][nf][3]);
        }
    }
}

// ---------------- CSR aggregation: warp per target node, fp16 gather ----------
// Layer 1 (D=128, RELUB): out_h = fp16(relu(agg + b[col]))
// Layer 2 (D=64,  !RELUB): out_f = agg + b[col]   (fp32 d_out)
template<int D, bool RELUB>
__global__ void __launch_bounds__(256)
k_agg(const __half* __restrict__ h, __half* __restrict__ out_h,
      float* __restrict__ out_f, const float* __restrict__ bias) {
    int gw   = (blockIdx.x * 256 + threadIdx.x) >> 5;
    int lane = threadIdx.x & 31;
    if (gw >= NN) return;
    const float dt  = g_dinv[gw];
    const int   beg = g_rowptr[gw];
    const int   end = beg + ((int)g_deg[gw] - 1);
    const uint2* hp = (const uint2*)h;

    if (D == 128) {
        const int c = lane;                       // 32 uint2 chunks = full row
        float4 acc = up4(hp[(size_t)gw * 32 + c]);
        float ws = dt * dt;
        acc.x *= ws; acc.y *= ws; acc.z *= ws; acc.w *= ws;
        int e = beg;
        for (; e + 4 <= end; e += 4) {            // 4 edges in flight
            int s0 = g_eidx[e],     s1 = g_eidx[e + 1];
            int s2 = g_eidx[e + 2], s3 = g_eidx[e + 3];
            float w0 = dt * g_dinv[s0], w1 = dt * g_dinv[s1];
            float w2 = dt * g_dinv[s2], w3 = dt * g_dinv[s3];
            float4 v0 = up4(hp[(size_t)s0 * 32 + c]);
            float4 v1 = up4(hp[(size_t)s1 * 32 + c]);
            float4 v2 = up4(hp[(size_t)s2 * 32 + c]);
            float4 v3 = up4(hp[(size_t)s3 * 32 + c]);
            acc.x += w0 * v0.x + w1 * v1.x + w2 * v2.x + w3 * v3.x;
            acc.y += w0 * v0.y + w1 * v1.y + w2 * v2.y + w3 * v3.y;
            acc.z += w0 * v0.z + w1 * v1.z + w2 * v2.z + w3 * v3.z;
            acc.w += w0 * v0.w + w1 * v1.w + w2 * v2.w + w3 * v3.w;
        }
        for (; e < end; e++) {
            int s = g_eidx[e];
            float wv = dt * g_dinv[s];
            float4 v = up4(hp[(size_t)s * 32 + c]);
            acc.x += wv * v.x; acc.y += wv * v.y;
            acc.z += wv * v.z; acc.w += wv * v.w;
        }
        if (RELUB) {
            float4 b = ((const float4*)bias)[c];
            acc.x = fmaxf(acc.x + b.x, 0.f);
            acc.y = fmaxf(acc.y + b.y, 0.f);
            acc.z = fmaxf(acc.z + b.z, 0.f);
            acc.w = fmaxf(acc.w + b.w, 0.f);
            __half2 p0 = __floats2half2_rn(acc.x, acc.y);
            __half2 p1 = __floats2half2_rn(acc.z, acc.w);
            ((uint2*)out_h)[(size_t)gw * 32 + c] =
                make_uint2(*(uint32_t*)&p0, *(uint32_t*)&p1);
        } else {
            ((float4*)out_f)[(size_t)gw * 32 + c] = acc;
        }
    } else {                                      // D=64: 16 chunks, 2 edges in flight
        const int c    = lane & 15;
        const int half = lane >> 4;
        float4 acc = make_float4(0.f, 0.f, 0.f, 0.f);
        if (half == 0) {
            acc = up4(hp[(size_t)gw * 16 + c]);
            float ws = dt * dt;
            acc.x *= ws; acc.y *= ws; acc.z *= ws; acc.w *= ws;
            float4 b = ((const float4*)bias)[c];
            acc.x += b.x; acc.y += b.y; acc.z += b.z; acc.w += b.w;
        }
        for (int e = beg + half; e < end; e += 2) {
            int s = g_eidx[e];
            float wv = dt * g_dinv[s];
            float4 v = up4(hp[(size_t)s * 16 + c]);
            acc.x += wv * v.x; acc.y += wv * v.y;
            acc.z += wv * v.z; acc.w += wv * v.w;
        }
        acc.x += __shfl_down_sync(0xffffffffu, acc.x, 16);
        acc.y += __shfl_down_sync(0xffffffffu, acc.y, 16);
        acc.z += __shfl_down_sync(0xffffffffu, acc.z, 16);
        acc.w += __shfl_down_sync(0xffffffffu, acc.w, 16);
        if (half == 0) ((float4*)out_f)[(size_t)gw * 16 + c] = acc;
    }
}

// ---------------- launcher ----------------------------------------------------
extern "C" void kernel_launch(void* const* d_in, const int* in_sizes, int n_in,
                              void* d_out, int out_size) {
    const float* x  = (const float*)d_in[0];
    const int*   ei = (const int*)  d_in[1];
    const float* W1 = (const float*)d_in[2];
    const float* b1 = (const float*)d_in[3];
    const float* W2 = (const float*)d_in[4];
    const float* b2 = (const float*)d_in[5];
    float* out = (float*)d_out;

    const int* src = ei;
    const int* tgt = ei + NE;

    void *p_h1, *p_a1h, *p_h2;
    cudaGetSymbolAddress(&p_h1,  g_h1);
    cudaGetSymbolAddress(&p_a1h, g_a1h);
    cudaGetSymbolAddress(&p_h2,  g_h2);
    __half* h1  = (__half*)p_h1;
    __half* a1h = (__half*)p_a1h;
    __half* h2  = (__half*)p_h2;

    constexpr int KW = (KDIM + 8) / 2;
    const int smem1 = (2 * 256 * KW + 2 * 128 * KW) * 4;     // 208896 B
    const int smem2 = (2 * 256 * KW + 2 * 64  * KW) * 4;     // 174080 B
    cudaFuncSetAttribute((const void*)k_gemm_bf<128, 4, 4, 4, float>,
                         cudaFuncAttributeMaxDynamicSharedMemorySize, smem1);
    cudaFuncSetAttribute((const void*)k_gemm_bf<64, 8, 2, 4, __half>,
                         cudaFuncAttributeMaxDynamicSharedMemorySize, smem2);

    static cudaStream_t s_csr = nullptr;
    static cudaEvent_t  ev_fork = nullptr, ev_join = nullptr;
    if (!s_csr) {
        cudaStreamCreateWithFlags(&s_csr, cudaStreamNonBlocking);
        cudaEventCreateWithFlags(&ev_fork, cudaEventDisableTiming);
        cudaEventCreateWithFlags(&ev_join, cudaEventDisableTiming);
    }

    // fork: CSR build runs concurrently with GEMM1
    cudaEventRecord(ev_fork, 0);
    cudaStreamWaitEvent(s_csr, ev_fork, 0);
    k_init_deg  <<<(NN + 255) / 256, 256, 0, s_csr>>>();
    k_deg       <<<(NE + 255) / 256, 256, 0, s_csr>>>(tgt);
    k_scan_block<<<NB_SCAN, 256, 0, s_csr>>>();
    k_scan_spine<<<1, 128, 0, s_csr>>>();
    k_scan_add  <<<(NN + 255) / 256, 256, 0, s_csr>>>();
    k_fill      <<<(NE + 255) / 256, 256, 0, s_csr>>>(src, tgt);
    cudaEventRecord(ev_join, s_csr);

    // GEMM1 on main stream (independent of CSR)
    k_gemm_bf<128, 4, 4, 4, float><<<(NN + 255) / 256, 512, smem1>>>(x, W1, h1);

    // join, then: a1h = fp16(relu(agg(h1) + b1)) ; h2 = a1h @ W2 ; out = agg(h2) + b2
    cudaStreamWaitEvent(0, ev_join, 0);
    k_agg<128, true><<<(NN * 32 + 255) / 256, 256>>>(h1, a1h, nullptr, b1);
    k_gemm_bf<64, 8, 2, 4, __half><<<(NN + 255) / 256, 512, smem2>>>(a1h, W2, h2);
    k_agg<64, false><<<(NN * 32 + 255) / 256, 256>>>(h2, nullptr, out, b2);
}